// round 1
// baseline (speedup 1.0000x reference)
#include <cuda_runtime.h>
#include <math.h>
#include <stddef.h>

#define NHEADS 8
#define DIMH   64
#define NTOK   8192
#define NBATCH 2
#define BHN    16          // batch*heads
#define ML     256         // landmarks
#define LGRP   32          // tokens per landmark
#define DIM    512

// ---------------- scratch (device globals; allocation-free) ----------------
__device__ float g_q [BHN*NTOK*DIMH];
__device__ float g_k [BHN*NTOK*DIMH];
__device__ float g_v [BHN*NTOK*DIMH];
__device__ float g_ql[BHN*ML*DIMH];
__device__ float g_kl[BHN*ML*DIMH];
__device__ float g_attn1[33554432];   // [bh][8192][256]
__device__ float g_attn3[33554432];   // [bh][256][8192]
__device__ float g_a2 [BHN*ML*ML];
__device__ float g_xz [BHN*ML*ML];
__device__ float g_w  [BHN*ML*ML];
__device__ float g_u  [BHN*ML*ML];
__device__ float g_z  [BHN*ML*ML];
__device__ float g_z2 [BHN*ML*ML];
__device__ float g_t3p[16*BHN*ML*DIMH];  // split-K partials
__device__ float g_t3 [BHN*ML*DIMH];
__device__ float g_t2 [BHN*ML*DIMH];
__device__ float g_oh [BHN*NTOK*DIMH];
__device__ int   g_scal[2];

// ---------------- functors ----------------
struct AP {                 // row-major A [*, ld], batch stride bs (elements)
    const float* p; int ld; size_t bs;
    __device__ __forceinline__ float4 load4(int bz, int r, int k) const {
        return *(const float4*)(p + (size_t)bz*bs + (size_t)r*ld + k);
    }
};
struct BP {                 // row-major B [K, ld]
    const float* p; int ld; size_t bs;
    __device__ __forceinline__ float4 load4(int bz, int k, int n) const {
        return *(const float4*)(p + (size_t)bz*bs + (size_t)k*ld + n);
    }
};
struct BDiag {              // alpha*I - P, P is [256,256] per batch
    const float* p; float alpha;
    __device__ __forceinline__ float4 load4(int bz, int k, int n) const {
        float4 v = *(const float4*)(p + (size_t)bz*65536 + (size_t)k*256 + n);
        float4 r;
        r.x = ((k==n+0)?alpha:0.f) - v.x;
        r.y = ((k==n+1)?alpha:0.f) - v.y;
        r.z = ((k==n+2)?alpha:0.f) - v.z;
        r.w = ((k==n+3)?alpha:0.f) - v.w;
        return r;
    }
};
struct BT {                 // B stored [N, K] row-major (use B^T)
    const float* p; int ld; size_t bs;
    __device__ __forceinline__ float4 load4T(int bz, int c, int k) const {
        return *(const float4*)(p + (size_t)bz*bs + (size_t)c*ld + k);
    }
};
struct ES {                 // plain (scaled) store
    float* p; int ld; size_t bs; float scale;
    __device__ __forceinline__ void store(int bz, int r, int c, float v) const {
        p[(size_t)bz*bs + (size_t)r*ld + c] = v*scale;
    }
};
struct EDiag {              // alpha*I - acc, [256,256] per batch
    float* p; float alpha;
    __device__ __forceinline__ void store(int bz, int r, int c, float v) const {
        p[(size_t)bz*65536 + (size_t)r*256 + c] = ((r==c)?alpha:0.f) - v;
    }
};
struct EQKV {               // scatter qkv -> head-major, scale q by 0.125
    float* q; float* k; float* v;
    __device__ __forceinline__ void store(int bz, int r, int c, float acc) const {
        int b = r >> 13, t = r & (NTOK-1);
        int which = c >> 9, head = (c >> 6) & 7, dd = c & 63;
        float* dst = (which==0) ? q : ((which==1) ? k : v);
        if (which == 0) acc *= 0.125f;
        dst[(((size_t)(b*8+head))*NTOK + t)*64 + dd] = acc;
    }
};
struct ASplit {             // attn3 [bh][256][8192], bz = bh*16 + split
    const float* p;
    __device__ __forceinline__ float4 load4(int bz, int r, int k) const {
        int bh = bz >> 4, sp = bz & 15;
        return *(const float4*)(p + ((size_t)bh*ML + r)*NTOK + sp*512 + k);
    }
};
struct BSplit {             // v [bh][8192][64]
    const float* p;
    __device__ __forceinline__ float4 load4(int bz, int k, int n) const {
        int bh = bz >> 4, sp = bz & 15;
        return *(const float4*)(p + ((size_t)bh*NTOK + sp*512 + k)*64 + n);
    }
};
struct EPart {              // partial store [sp][bh][256][64]
    float* p;
    __device__ __forceinline__ void store(int bz, int r, int c, float v) const {
        int bh = bz >> 4, sp = bz & 15;
        p[(((size_t)sp*BHN + bh)*ML + r)*64 + c] = v;
    }
};
struct AGather {            // oh [bh][t][dd]; row=(b,t), k=head*64+dd
    const float* p;
    __device__ __forceinline__ float4 load4(int bz, int r, int k) const {
        int b = r >> 13, t = r & (NTOK-1), head = k >> 6, dd = k & 63;
        return *(const float4*)(p + (((size_t)(b*8+head))*NTOK + t)*64 + dd);
    }
};
struct EFin {               // out = x + acc + b_out
    const float* x; const float* bo; float* out;
    __device__ __forceinline__ void store(int bz, int r, int c, float v) const {
        size_t i = (size_t)r*DIM + c;
        out[i] = x[i] + bo[c] + v;
    }
};

// ---------------- generic 64x64x16 GEMM (NN) ----------------
template<class FA, class FB, class FE>
__global__ __launch_bounds__(256) void gemm_nn(FA fa, FB fb, FE fe, int K) {
    __shared__ __align__(16) float As[16][64];
    __shared__ __align__(16) float Bs[16][64];
    const int tid = threadIdx.x;
    const int tx = tid & 15, ty = tid >> 4;
    const int m0 = blockIdx.y << 6, n0 = blockIdx.x << 6, bz = blockIdx.z;
    const int am = tid >> 2,  akq = (tid & 3)  << 2;
    const int bk = tid >> 4,  bnq = (tid & 15) << 2;
    float acc[4][4] = {};
    for (int k0 = 0; k0 < K; k0 += 16) {
        float4 av = fa.load4(bz, m0 + am, k0 + akq);
        As[akq+0][am] = av.x; As[akq+1][am] = av.y;
        As[akq+2][am] = av.z; As[akq+3][am] = av.w;
        float4 bv = fb.load4(bz, k0 + bk, n0 + bnq);
        *(float4*)&Bs[bk][bnq] = bv;
        __syncthreads();
#pragma unroll
        for (int kk = 0; kk < 16; kk++) {
            float4 a = *(const float4*)&As[kk][ty << 2];
            float4 b = *(const float4*)&Bs[kk][tx << 2];
            float ar[4] = {a.x, a.y, a.z, a.w};
            float br[4] = {b.x, b.y, b.z, b.w};
#pragma unroll
            for (int i = 0; i < 4; i++)
#pragma unroll
                for (int j = 0; j < 4; j++) acc[i][j] += ar[i] * br[j];
        }
        __syncthreads();
    }
#pragma unroll
    for (int i = 0; i < 4; i++)
#pragma unroll
        for (int j = 0; j < 4; j++)
            fe.store(bz, m0 + (ty << 2) + i, n0 + (tx << 2) + j, acc[i][j]);
}

// ---------------- generic 64x64x16 GEMM (NT: B stored [N,K]) ----------------
template<class FA, class FB, class FE>
__global__ __launch_bounds__(256) void gemm_nt(FA fa, FB fb, FE fe, int K) {
    __shared__ __align__(16) float As[16][64];
    __shared__ __align__(16) float Bs[16][64];
    const int tid = threadIdx.x;
    const int tx = tid & 15, ty = tid >> 4;
    const int m0 = blockIdx.y << 6, n0 = blockIdx.x << 6, bz = blockIdx.z;
    const int am = tid >> 2,  akq = (tid & 3) << 2;
    const int bc = tid & 63,  bkq = (tid >> 6) << 2;
    float acc[4][4] = {};
    for (int k0 = 0; k0 < K; k0 += 16) {
        float4 av = fa.load4(bz, m0 + am, k0 + akq);
        As[akq+0][am] = av.x; As[akq+1][am] = av.y;
        As[akq+2][am] = av.z; As[akq+3][am] = av.w;
        float4 bv = fb.load4T(bz, n0 + bc, k0 + bkq);
        Bs[bkq+0][bc] = bv.x; Bs[bkq+1][bc] = bv.y;
        Bs[bkq+2][bc] = bv.z; Bs[bkq+3][bc] = bv.w;
        __syncthreads();
#pragma unroll
        for (int kk = 0; kk < 16; kk++) {
            float4 a = *(const float4*)&As[kk][ty << 2];
            float4 b = *(const float4*)&Bs[kk][tx << 2];
            float ar[4] = {a.x, a.y, a.z, a.w};
            float br[4] = {b.x, b.y, b.z, b.w};
#pragma unroll
            for (int i = 0; i < 4; i++)
#pragma unroll
                for (int j = 0; j < 4; j++) acc[i][j] += ar[i] * br[j];
        }
        __syncthreads();
    }
#pragma unroll
    for (int i = 0; i < 4; i++)
#pragma unroll
        for (int j = 0; j < 4; j++)
            fe.store(bz, m0 + (ty << 2) + i, n0 + (tx << 2) + j, acc[i][j]);
}

// ---------------- sim1 = softmax(q @ kl^T) fused, BN=256 = full row --------
__global__ __launch_bounds__(256) void sim1_softmax(
        const float* __restrict__ q, const float* __restrict__ kl,
        float* __restrict__ attn1) {
    const int bh = blockIdx.z;
    const int m0 = blockIdx.y << 5;          // 32 rows per block
    const float* Q  = q  + (size_t)bh * NTOK * 64;
    const float* KL = kl + (size_t)bh * ML * 64;
    float* O = attn1 + ((size_t)bh * NTOK + m0) * 256;
    __shared__ __align__(16) float As[16][32];
    __shared__ __align__(16) float Bs[16][256];
    __shared__ float red[32][33];
    const int tid = threadIdx.x;
    const int tx = tid & 31, ty = tid >> 5;  // cols x8, rows x4
    const int am = tid >> 3, akq = (tid & 7) << 1;
    float acc[4][8] = {};
    for (int k0 = 0; k0 < 64; k0 += 16) {
        float2 av = *(const float2*)(Q + (size_t)(m0 + am)*64 + k0 + akq);
        As[akq][am] = av.x; As[akq+1][am] = av.y;
        const float* kp = KL + (size_t)tid*64 + k0;
#pragma unroll
        for (int kq = 0; kq < 16; kq += 4) {
            float4 b = *(const float4*)(kp + kq);
            Bs[kq+0][tid] = b.x; Bs[kq+1][tid] = b.y;
            Bs[kq+2][tid] = b.z; Bs[kq+3][tid] = b.w;
        }
        __syncthreads();
#pragma unroll
        for (int kk = 0; kk < 16; kk++) {
            float4 a  = *(const float4*)&As[kk][ty << 2];
            float4 b0 = *(const float4*)&Bs[kk][tx << 3];
            float4 b1 = *(const float4*)&Bs[kk][(tx << 3) + 4];
            float ar[4] = {a.x, a.y, a.z, a.w};
            float br[8] = {b0.x, b0.y, b0.z, b0.w, b1.x, b1.y, b1.z, b1.w};
#pragma unroll
            for (int i = 0; i < 4; i++)
#pragma unroll
                for (int j = 0; j < 8; j++) acc[i][j] += ar[i]*br[j];
        }
        __syncthreads();
    }
    // row-wise softmax over 256 (each row owned by 32 tx threads)
#pragma unroll
    for (int i = 0; i < 4; i++) {
        float lm = acc[i][0];
#pragma unroll
        for (int j = 1; j < 8; j++) lm = fmaxf(lm, acc[i][j]);
        red[(ty<<2)+i][tx] = lm;
    }
    __syncthreads();
    float rmax[4];
#pragma unroll
    for (int i = 0; i < 4; i++) {
        int r = (ty<<2)+i; float m = red[r][0];
#pragma unroll
        for (int t = 1; t < 32; t++) m = fmaxf(m, red[r][t]);
        rmax[i] = m;
    }
    __syncthreads();
#pragma unroll
    for (int i = 0; i < 4; i++) {
        float s = 0.f;
#pragma unroll
        for (int j = 0; j < 8; j++) { acc[i][j] = __expf(acc[i][j] - rmax[i]); s += acc[i][j]; }
        red[(ty<<2)+i][tx] = s;
    }
    __syncthreads();
#pragma unroll
    for (int i = 0; i < 4; i++) {
        int r = (ty<<2)+i; float s = 0.f;
#pragma unroll
        for (int t = 0; t < 32; t++) s += red[r][t];
        float rinv = 1.f / s;
        float4 o0 = {acc[i][0]*rinv, acc[i][1]*rinv, acc[i][2]*rinv, acc[i][3]*rinv};
        float4 o1 = {acc[i][4]*rinv, acc[i][5]*rinv, acc[i][6]*rinv, acc[i][7]*rinv};
        *(float4*)(O + (size_t)r*256 + (tx << 3))     = o0;
        *(float4*)(O + (size_t)r*256 + (tx << 3) + 4) = o1;
    }
}

// ---------------- small kernels ----------------
__global__ void init_scal_k(int* scal) { if (threadIdx.x < 2) scal[threadIdx.x] = 0; }

__global__ __launch_bounds__(256) void landmarks_k(
        const float* __restrict__ q, const float* __restrict__ k,
        float* __restrict__ ql, float* __restrict__ kl) {
    int idx = blockIdx.x * 256 + threadIdx.x;      // 16*256*64 = 262144
    int dd = idx & 63, j = (idx >> 6) & 255, bh = idx >> 14;
    const float* qp = q + ((size_t)bh*NTOK + (size_t)j*LGRP)*64 + dd;
    const float* kp = k + ((size_t)bh*NTOK + (size_t)j*LGRP)*64 + dd;
    float sq = 0.f, sk = 0.f;
#pragma unroll
    for (int t = 0; t < LGRP; t++) { sq += qp[(size_t)t*64]; sk += kp[(size_t)t*64]; }
    ql[idx] = sq * (1.f/LGRP);
    kl[idx] = sk * (1.f/LGRP);
}

__global__ __launch_bounds__(256) void softmax256_k(float* a) {
    float* p = a + (size_t)blockIdx.x * 256;
    int tid = threadIdx.x;
    float v = p[tid];
    __shared__ float red[256];
    red[tid] = v; __syncthreads();
    for (int s = 128; s > 0; s >>= 1) { if (tid < s) red[tid] = fmaxf(red[tid], red[tid+s]); __syncthreads(); }
    float m = red[0]; __syncthreads();
    float e = __expf(v - m);
    red[tid] = e; __syncthreads();
    for (int s = 128; s > 0; s >>= 1) { if (tid < s) red[tid] += red[tid+s]; __syncthreads(); }
    p[tid] = e / red[0];
}

__global__ __launch_bounds__(256) void scal_reduce_k(const float* __restrict__ a2, int* scal) {
    int idx = blockIdx.x, bh = blockIdx.y, mode = blockIdx.z, tid = threadIdx.x;
    const float* base = a2 + (size_t)bh * 65536;
    float v = (mode == 0) ? base[(size_t)idx*256 + tid] : base[(size_t)tid*256 + idx];
    __shared__ float red[256];
    red[tid] = v; __syncthreads();
    for (int s = 128; s > 0; s >>= 1) { if (tid < s) red[tid] += red[tid+s]; __syncthreads(); }
    if (tid == 0) atomicMax(&scal[mode], __float_as_int(red[0]));
}

__global__ __launch_bounds__(256) void zinit_k(const float* __restrict__ a2,
                                               const int* __restrict__ scal,
                                               float* __restrict__ z) {
    size_t idx = (size_t)blockIdx.x * 256 + threadIdx.x;   // 16*256*256
    float col = __int_as_float(scal[0]), row = __int_as_float(scal[1]);
    float rcp = 1.f / (col * row);
    int j = (int)(idx & 255), i = (int)((idx >> 8) & 255);
    size_t bh = idx >> 16;
    z[idx] = a2[(bh << 16) + (size_t)j*256 + i] * rcp;
}

__global__ __launch_bounds__(256) void softmax8192_k(float* a) {
    __shared__ float buf[8192];
    __shared__ float red[256];
    float* p = a + (size_t)blockIdx.x * 8192;
    int tid = threadIdx.x;
    float lm = -1e30f;
    for (int j = tid; j < 8192; j += 256) { float v = p[j]; buf[j] = v; lm = fmaxf(lm, v); }
    red[tid] = lm; __syncthreads();
    for (int s = 128; s > 0; s >>= 1) { if (tid < s) red[tid] = fmaxf(red[tid], red[tid+s]); __syncthreads(); }
    float m = red[0]; __syncthreads();
    float ls = 0.f;
    for (int j = tid; j < 8192; j += 256) { float e = __expf(buf[j] - m); buf[j] = e; ls += e; }
    red[tid] = ls; __syncthreads();
    for (int s = 128; s > 0; s >>= 1) { if (tid < s) red[tid] += red[tid+s]; __syncthreads(); }
    float rinv = 1.f / red[0];
    for (int j = tid; j < 8192; j += 256) p[j] = buf[j] * rinv;
}

__global__ __launch_bounds__(256) void t3_reduce_k(const float* __restrict__ part,
                                                   float* __restrict__ t3) {
    int idx = blockIdx.x * 256 + threadIdx.x;   // 262144
    float s = 0.f;
#pragma unroll
    for (int sp = 0; sp < 16; sp++) s += part[(size_t)sp*262144 + idx];
    t3[idx] = s;
}

__global__ __launch_bounds__(256) void conv_add_k(const float* __restrict__ v,
                                                  const float* __restrict__ wc,
                                                  float* __restrict__ oh) {
    size_t idx = (size_t)blockIdx.x * 256 + threadIdx.x;   // 16*8192*64
    int dd = (int)(idx & 63);
    int i  = (int)((idx >> 6) & (NTOK-1));
    int bh = (int)(idx >> 19);
    int h = bh & 7;
    const float* vb = v + ((size_t)bh * NTOK) * 64 + dd;
    float s = 0.f;
#pragma unroll
    for (int t = 0; t < 33; t++) {
        int src = i + t - 16;
        if (src >= 0 && src < NTOK) s += wc[h*33 + t] * vb[(size_t)src*64];
    }
    oh[idx] += s;
}

// ---------------- orchestration ----------------
extern "C" void kernel_launch(void* const* d_in, const int* in_sizes, int n_in,
                              void* d_out, int out_size) {
    (void)in_sizes; (void)n_in; (void)out_size;
    const float* x      = (const float*)d_in[0];
    const float* w_qkv  = (const float*)d_in[1];
    const float* w_out  = (const float*)d_in[2];
    const float* b_out  = (const float*)d_in[3];
    const float* w_conv = (const float*)d_in[4];
    float* out = (float*)d_out;

    float *q,*k,*v,*ql,*kl,*a1,*a3,*a2,*xz,*w,*u,*z,*z2,*t3p,*t3,*t2,*oh;
    int* scal;
    cudaGetSymbolAddress((void**)&q,  g_q);
    cudaGetSymbolAddress((void**)&k,  g_k);
    cudaGetSymbolAddress((void**)&v,  g_v);
    cudaGetSymbolAddress((void**)&ql, g_ql);
    cudaGetSymbolAddress((void**)&kl, g_kl);
    cudaGetSymbolAddress((void**)&a1, g_attn1);
    cudaGetSymbolAddress((void**)&a3, g_attn3);
    cudaGetSymbolAddress((void**)&a2, g_a2);
    cudaGetSymbolAddress((void**)&xz, g_xz);
    cudaGetSymbolAddress((void**)&w,  g_w);
    cudaGetSymbolAddress((void**)&u,  g_u);
    cudaGetSymbolAddress((void**)&z,  g_z);
    cudaGetSymbolAddress((void**)&z2, g_z2);
    cudaGetSymbolAddress((void**)&t3p,g_t3p);
    cudaGetSymbolAddress((void**)&t3, g_t3);
    cudaGetSymbolAddress((void**)&t2, g_t2);
    cudaGetSymbolAddress((void**)&oh, g_oh);
    cudaGetSymbolAddress((void**)&scal, g_scal);

    init_scal_k<<<1, 32>>>(scal);

    // 1. QKV projection: [16384,512]@[512,1536] scattered to head-major q/k/v
    gemm_nn<<<dim3(24, 256, 1), 256>>>(AP{x, DIM, 0}, BP{w_qkv, 1536, 0},
                                       EQKV{q, k, v}, DIM);
    // 2. landmark means
    landmarks_k<<<1024, 256>>>(q, k, ql, kl);

    // 3. sim2 = ql @ kl^T  -> softmax -> attn2
    gemm_nt<<<dim3(4, 4, BHN), 256>>>(AP{ql, 64, (size_t)ML*64},
                                      BT{kl, 64, (size_t)ML*64},
                                      ES{a2, 256, 65536, 1.f}, 64);
    softmax256_k<<<BHN*ML, 256>>>(a2);

    // 4. pinv init: scalars + z0 = attn2^T / (col*row)
    scal_reduce_k<<<dim3(256, BHN, 2), 256>>>(a2, scal);
    zinit_k<<<4096, 256>>>(a2, scal, z);

    // 5. Newton–Schulz iterations (4 batched 256^3 GEMMs each)
    for (int it = 0; it < 6; it++) {
        float* zin  = (it & 1) ? z2 : z;
        float* zout = (it & 1) ? z  : z2;
        gemm_nn<<<dim3(4,4,BHN),256>>>(AP{a2,256,65536}, BP{zin,256,65536},
                                       ES{xz,256,65536,1.f}, 256);
        gemm_nn<<<dim3(4,4,BHN),256>>>(AP{xz,256,65536}, BDiag{xz,7.f},
                                       EDiag{w,15.f}, 256);
        gemm_nn<<<dim3(4,4,BHN),256>>>(AP{xz,256,65536}, BP{w,256,65536},
                                       EDiag{u,13.f}, 256);
        gemm_nn<<<dim3(4,4,BHN),256>>>(AP{zin,256,65536}, BP{u,256,65536},
                                       ES{zout,256,65536,0.25f}, 256);
    }
    // after 6 iters final z lives in g_z

    // 6. attn1 = softmax(q @ kl^T) fused
    sim1_softmax<<<dim3(1, 256, BHN), 256>>>(q, kl, a1);

    // 7. sim3 = ql @ k^T -> softmax over n=8192
    gemm_nt<<<dim3(128, 4, BHN), 256>>>(AP{ql, 64, (size_t)ML*64},
                                        BT{k, 64, (size_t)NTOK*64},
                                        ES{a3, NTOK, (size_t)ML*NTOK, 1.f}, 64);
    softmax8192_k<<<BHN*ML, 256>>>(a3);

    // 8. t3 = attn3 @ v  (split-K x16 + reduce)
    gemm_nn<<<dim3(1, 4, BHN*16), 256>>>(ASplit{a3}, BSplit{v}, EPart{t3p}, 512);
    t3_reduce_k<<<1024, 256>>>(t3p, t3);

    // 9. t2 = z @ t3
    gemm_nn<<<dim3(1, 4, BHN), 256>>>(AP{z, 256, 65536}, BP{t3, 64, (size_t)ML*64},
                                      ES{t2, 64, (size_t)ML*64, 1.f}, 256);

    // 10. oh = attn1 @ t2
    gemm_nn<<<dim3(1, 128, BHN), 256>>>(AP{a1, 256, (size_t)NTOK*256},
                                        BP{t2, 64, (size_t)ML*64},
                                        ES{oh, 64, (size_t)NTOK*64, 1.f}, 256);

    // 11. residual depthwise conv over sequence, added into oh
    conv_add_k<<<32768, 256>>>(v, w_conv, oh);

    // 12. y = x + (oh gathered to [b,n,512]) @ w_out + b_out
    gemm_nn<<<dim3(8, 256, 1), 256>>>(AGather{oh}, BP{w_out, DIM, 0},
                                      EFin{x, b_out, out}, DIM);
}

// round 3
// speedup vs baseline: 1.4518x; 1.4518x over previous
#include <cuda_runtime.h>
#include <math.h>
#include <stddef.h>

#define NHEADS 8
#define DIMH   64
#define NTOK   8192
#define NBATCH 2
#define BHN    16          // batch*heads
#define ML     256         // landmarks
#define LGRP   32          // tokens per landmark
#define DIM    512

// ---------------- scratch (device globals; allocation-free) ----------------
__device__ float g_q [BHN*NTOK*DIMH];
__device__ float g_k [BHN*NTOK*DIMH];
__device__ float g_v [BHN*NTOK*DIMH];
__device__ float g_ql[BHN*ML*DIMH];
__device__ float g_kl[BHN*ML*DIMH];
__device__ float g_attn1[33554432];   // [bh][8192][256]
__device__ float g_attn3[33554432];   // [bh][256][8192]
__device__ float g_a2 [BHN*ML*ML];
__device__ float g_xz [BHN*ML*ML];
__device__ float g_w  [BHN*ML*ML];
__device__ float g_u  [BHN*ML*ML];
__device__ float g_z  [BHN*ML*ML];
__device__ float g_z2 [BHN*ML*ML];
__device__ float g_t3p[16*BHN*ML*DIMH];  // split-K partials
__device__ float g_t3 [BHN*ML*DIMH];
__device__ float g_t2 [BHN*ML*DIMH];
__device__ float g_oh [BHN*NTOK*DIMH];
__device__ int   g_scal[2];

// ---------------- tf32 mma primitives ----------------
__device__ __forceinline__ unsigned f2tf(float f) {
    unsigned u; asm("cvt.rna.tf32.f32 %0, %1;" : "=r"(u) : "f"(f)); return u;
}
__device__ __forceinline__ void mma_tf32(float* d, const unsigned* a, const unsigned* b) {
    asm volatile("mma.sync.aligned.m16n8k8.row.col.f32.tf32.tf32.f32 "
        "{%0,%1,%2,%3}, {%4,%5,%6,%7}, {%8,%9}, {%0,%1,%2,%3};"
        : "+f"(d[0]), "+f"(d[1]), "+f"(d[2]), "+f"(d[3])
        : "r"(a[0]), "r"(a[1]), "r"(a[2]), "r"(a[3]), "r"(b[0]), "r"(b[1]));
}

// ---------------- functors ----------------
struct AP {                 // row-major A [*, ld], batch stride bs (elements)
    const float* p; int ld; size_t bs;
    __device__ __forceinline__ float4 load4(int bz, int r, int k) const {
        return *(const float4*)(p + (size_t)bz*bs + (size_t)r*ld + k);
    }
};
struct BP {                 // row-major B [K, ld]
    const float* p; int ld; size_t bs;
    __device__ __forceinline__ float4 load4(int bz, int k, int n) const {
        return *(const float4*)(p + (size_t)bz*bs + (size_t)k*ld + n);
    }
};
struct BDiag {              // alpha*I - P, P is [256,256] per batch
    const float* p; float alpha;
    __device__ __forceinline__ float4 load4(int bz, int k, int n) const {
        float4 v = *(const float4*)(p + (size_t)bz*65536 + (size_t)k*256 + n);
        float4 r;
        r.x = ((k==n+0)?alpha:0.f) - v.x;
        r.y = ((k==n+1)?alpha:0.f) - v.y;
        r.z = ((k==n+2)?alpha:0.f) - v.z;
        r.w = ((k==n+3)?alpha:0.f) - v.w;
        return r;
    }
};
struct BTmat {              // B stored [N, K] row-major (use B^T)
    const float* p; int ld; size_t bs;
    __device__ __forceinline__ float4 load4T(int bz, int c, int k) const {
        return *(const float4*)(p + (size_t)bz*bs + (size_t)c*ld + k);
    }
};
struct ES {                 // plain (scaled) store
    float* p; int ld; size_t bs; float scale;
    __device__ __forceinline__ void store(int bz, int r, int c, float v) const {
        p[(size_t)bz*bs + (size_t)r*ld + c] = v*scale;
    }
};
struct EDiag {              // alpha*I - acc, [256,256] per batch
    float* p; float alpha;
    __device__ __forceinline__ void store(int bz, int r, int c, float v) const {
        p[(size_t)bz*65536 + (size_t)r*256 + c] = ((r==c)?alpha:0.f) - v;
    }
};
struct EQKV {               // scatter qkv -> head-major, scale q by 0.125
    float* q; float* k; float* v;
    __device__ __forceinline__ void store(int bz, int r, int c, float acc) const {
        int b = r >> 13, t = r & (NTOK-1);
        int which = c >> 9, head = (c >> 6) & 7, dd = c & 63;
        float* dst = (which==0) ? q : ((which==1) ? k : v);
        if (which == 0) acc *= 0.125f;
        dst[(((size_t)(b*8+head))*NTOK + t)*64 + dd] = acc;
    }
};
struct ASplit {             // attn3 [bh][256][8192], bz = bh*16 + split
    const float* p;
    __device__ __forceinline__ float4 load4(int bz, int r, int k) const {
        int bh = bz >> 4, sp = bz & 15;
        return *(const float4*)(p + ((size_t)bh*ML + r)*NTOK + sp*512 + k);
    }
};
struct BSplit {             // v [bh][8192][64]
    const float* p;
    __device__ __forceinline__ float4 load4(int bz, int k, int n) const {
        int bh = bz >> 4, sp = bz & 15;
        return *(const float4*)(p + ((size_t)bh*NTOK + sp*512 + k)*64 + n);
    }
};
struct EPart {              // partial store [sp][bh][256][64]
    float* p;
    __device__ __forceinline__ void store(int bz, int r, int c, float v) const {
        int bh = bz >> 4, sp = bz & 15;
        p[(((size_t)sp*BHN + bh)*ML + r)*64 + c] = v;
    }
};
struct AGather {            // oh [bh][t][dd]; row=(b,t), k=head*64+dd
    const float* p;
    __device__ __forceinline__ float4 load4(int bz, int r, int k) const {
        int b = r >> 13, t = r & (NTOK-1), head = k >> 6, dd = k & 63;
        return *(const float4*)(p + (((size_t)(b*8+head))*NTOK + t)*64 + dd);
    }
};
struct EFin {               // out = x + acc + b_out
    const float* x; const float* bo; float* out;
    __device__ __forceinline__ void store(int bz, int r, int c, float v) const {
        size_t i = (size_t)r*DIM + c;
        out[i] = x[i] + bo[c] + v;
    }
};

// ---------------- tensor-core tf32 GEMM template ----------------
// BK = 16. A cached k-major in smem (As[k][m]), B as Bs[k][n]; pad 4 gives
// stride ≡ 4 (mod 32) => fragment LDS is <=2-way bank conflicted.
// BT_LAYOUT=true means B global is [N,K] row-major (uses load4T).
template<int BM, int BN, int WM, int WN, bool BT_LAYOUT, class FA, class FB, class FE>
__global__ __launch_bounds__((BM/WM)*(BN/WN)*32)
void gemm_tc(FA fa, FB fb, FE fe, int K) {
    constexpr int WARPS_M = BM/WM, WARPS_N = BN/WN;
    constexpr int NTHR = WARPS_M*WARPS_N*32;
    constexpr int LDA = BM + 4, LDB = BN + 4;
    constexpr int MT = WM/16, NT = WN/8;
    __shared__ unsigned As[16][LDA];
    __shared__ unsigned Bs[16][LDB];
    const int tid = threadIdx.x;
    const int wid = tid >> 5, lane = tid & 31;
    const int qd = lane >> 2, tq = lane & 3;
    const int wm = (wid / WARPS_N) * WM, wn = (wid % WARPS_N) * WN;
    const int m0 = blockIdx.y * BM, n0 = blockIdx.x * BN, bz = blockIdx.z;

    float acc[MT][NT][4];
#pragma unroll
    for (int i = 0; i < MT; i++)
#pragma unroll
        for (int j = 0; j < NT; j++) {
            acc[i][j][0] = 0.f; acc[i][j][1] = 0.f;
            acc[i][j][2] = 0.f; acc[i][j][3] = 0.f;
        }

    for (int k0 = 0; k0 < K; k0 += 16) {
        // ---- A -> smem (transposed to k-major) ----
#pragma unroll
        for (int i = tid; i < BM*4; i += NTHR) {
            int m = i >> 2, kq = (i & 3) << 2;
            float4 v = fa.load4(bz, m0 + m, k0 + kq);
            As[kq+0][m] = f2tf(v.x); As[kq+1][m] = f2tf(v.y);
            As[kq+2][m] = f2tf(v.z); As[kq+3][m] = f2tf(v.w);
        }
        // ---- B -> smem ----
        if constexpr (BT_LAYOUT) {
#pragma unroll
            for (int i = tid; i < BN*4; i += NTHR) {
                int n = i >> 2, kq = (i & 3) << 2;
                float4 v = fb.load4T(bz, n0 + n, k0 + kq);
                Bs[kq+0][n] = f2tf(v.x); Bs[kq+1][n] = f2tf(v.y);
                Bs[kq+2][n] = f2tf(v.z); Bs[kq+3][n] = f2tf(v.w);
            }
        } else {
#pragma unroll
            for (int i = tid; i < BN*4; i += NTHR) {
                int k = i / (BN/4), nq = (i % (BN/4)) * 4;
                float4 v = fb.load4(bz, k0 + k, n0 + nq);
                Bs[k][nq+0] = f2tf(v.x); Bs[k][nq+1] = f2tf(v.y);
                Bs[k][nq+2] = f2tf(v.z); Bs[k][nq+3] = f2tf(v.w);
            }
        }
        __syncthreads();
#pragma unroll
        for (int ks = 0; ks < 16; ks += 8) {
            unsigned af[MT][4], bf[NT][2];
#pragma unroll
            for (int mt = 0; mt < MT; mt++) {
                int mm = wm + mt*16 + qd;
                af[mt][0] = As[ks+tq  ][mm];
                af[mt][1] = As[ks+tq  ][mm+8];
                af[mt][2] = As[ks+tq+4][mm];
                af[mt][3] = As[ks+tq+4][mm+8];
            }
#pragma unroll
            for (int nt = 0; nt < NT; nt++) {
                int nn = wn + nt*8 + qd;
                bf[nt][0] = Bs[ks+tq  ][nn];
                bf[nt][1] = Bs[ks+tq+4][nn];
            }
#pragma unroll
            for (int mt = 0; mt < MT; mt++)
#pragma unroll
                for (int nt = 0; nt < NT; nt++)
                    mma_tf32(acc[mt][nt], af[mt], bf[nt]);
        }
        __syncthreads();
    }
    // ---- epilogue ----
#pragma unroll
    for (int mt = 0; mt < MT; mt++)
#pragma unroll
        for (int nt = 0; nt < NT; nt++) {
            int r = m0 + wm + mt*16 + qd;
            int c = n0 + wn + nt*8 + tq*2;
            fe.store(bz, r,   c,   acc[mt][nt][0]);
            fe.store(bz, r,   c+1, acc[mt][nt][1]);
            fe.store(bz, r+8, c,   acc[mt][nt][2]);
            fe.store(bz, r+8, c+1, acc[mt][nt][3]);
        }
}

// ---------------- small kernels ----------------
__global__ void init_scal_k(int* scal) { if (threadIdx.x < 2) scal[threadIdx.x] = 0; }

__global__ __launch_bounds__(256) void landmarks_k(
        const float* __restrict__ q, const float* __restrict__ k,
        float* __restrict__ ql, float* __restrict__ kl) {
    int idx = blockIdx.x * 256 + threadIdx.x;      // 16*256*64 = 262144
    int dd = idx & 63, j = (idx >> 6) & 255, bh = idx >> 14;
    const float* qp = q + ((size_t)bh*NTOK + (size_t)j*LGRP)*64 + dd;
    const float* kp = k + ((size_t)bh*NTOK + (size_t)j*LGRP)*64 + dd;
    float sq = 0.f, sk = 0.f;
#pragma unroll
    for (int t = 0; t < LGRP; t++) { sq += qp[(size_t)t*64]; sk += kp[(size_t)t*64]; }
    ql[idx] = sq * (1.f/LGRP);
    kl[idx] = sk * (1.f/LGRP);
}

__global__ __launch_bounds__(256) void softmax256_k(float* a) {
    float* p = a + (size_t)blockIdx.x * 256;
    int tid = threadIdx.x;
    float v = p[tid];
    __shared__ float red[256];
    red[tid] = v; __syncthreads();
    for (int s = 128; s > 0; s >>= 1) { if (tid < s) red[tid] = fmaxf(red[tid], red[tid+s]); __syncthreads(); }
    float m = red[0]; __syncthreads();
    float e = __expf(v - m);
    red[tid] = e; __syncthreads();
    for (int s = 128; s > 0; s >>= 1) { if (tid < s) red[tid] += red[tid+s]; __syncthreads(); }
    p[tid] = e / red[0];
}

__global__ __launch_bounds__(256) void scal_reduce_k(const float* __restrict__ a2, int* scal) {
    int idx = blockIdx.x, bh = blockIdx.y, mode = blockIdx.z, tid = threadIdx.x;
    const float* base = a2 + (size_t)bh * 65536;
    float v = (mode == 0) ? base[(size_t)idx*256 + tid] : base[(size_t)tid*256 + idx];
    __shared__ float red[256];
    red[tid] = v; __syncthreads();
    for (int s = 128; s > 0; s >>= 1) { if (tid < s) red[tid] += red[tid+s]; __syncthreads(); }
    if (tid == 0) atomicMax(&scal[mode], __float_as_int(red[0]));
}

__global__ __launch_bounds__(256) void zinit_k(const float* __restrict__ a2,
                                               const int* __restrict__ scal,
                                               float* __restrict__ z) {
    size_t idx = (size_t)blockIdx.x * 256 + threadIdx.x;   // 16*256*256
    float col = __int_as_float(scal[0]), row = __int_as_float(scal[1]);
    float rcp = 1.f / (col * row);
    int j = (int)(idx & 255), i = (int)((idx >> 8) & 255);
    size_t bh = idx >> 16;
    z[idx] = a2[(bh << 16) + (size_t)j*256 + i] * rcp;
}

__global__ __launch_bounds__(256) void softmax8192_k(float* a) {
    __shared__ float buf[8192];
    __shared__ float red[256];
    float* p = a + (size_t)blockIdx.x * 8192;
    int tid = threadIdx.x;
    float lm = -1e30f;
    for (int j = tid; j < 8192; j += 256) { float v = p[j]; buf[j] = v; lm = fmaxf(lm, v); }
    red[tid] = lm; __syncthreads();
    for (int s = 128; s > 0; s >>= 1) { if (tid < s) red[tid] = fmaxf(red[tid], red[tid+s]); __syncthreads(); }
    float m = red[0]; __syncthreads();
    float ls = 0.f;
    for (int j = tid; j < 8192; j += 256) { float e = __expf(buf[j] - m); buf[j] = e; ls += e; }
    red[tid] = ls; __syncthreads();
    for (int s = 128; s > 0; s >>= 1) { if (tid < s) red[tid] += red[tid+s]; __syncthreads(); }
    float rinv = 1.f / red[0];
    for (int j = tid; j < 8192; j += 256) p[j] = buf[j] * rinv;
}

__global__ __launch_bounds__(256) void t3_reduce_k(const float* __restrict__ part,
                                                   float* __restrict__ t3) {
    int idx = blockIdx.x * 256 + threadIdx.x;   // 262144
    float s = 0.f;
#pragma unroll
    for (int sp = 0; sp < 16; sp++) s += part[(size_t)sp*262144 + idx];
    t3[idx] = s;
}

__global__ __launch_bounds__(256) void conv_add_k(const float* __restrict__ v,
                                                  const float* __restrict__ wc,
                                                  float* __restrict__ oh) {
    size_t idx = (size_t)blockIdx.x * 256 + threadIdx.x;   // 16*8192*64
    int dd = (int)(idx & 63);
    int i  = (int)((idx >> 6) & (NTOK-1));
    int bh = (int)(idx >> 19);
    int h = bh & 7;
    const float* vb = v + ((size_t)bh * NTOK) * 64 + dd;
    float s = 0.f;
#pragma unroll
    for (int t = 0; t < 33; t++) {
        int src = i + t - 16;
        if (src >= 0 && src < NTOK) s += wc[h*33 + t] * vb[(size_t)src*64];
    }
    oh[idx] += s;
}

// ---------------- orchestration ----------------
extern "C" void kernel_launch(void* const* d_in, const int* in_sizes, int n_in,
                              void* d_out, int out_size) {
    (void)in_sizes; (void)n_in; (void)out_size;
    const float* x      = (const float*)d_in[0];
    const float* w_qkv  = (const float*)d_in[1];
    const float* w_out  = (const float*)d_in[2];
    const float* b_out  = (const float*)d_in[3];
    const float* w_conv = (const float*)d_in[4];
    float* out = (float*)d_out;

    float *q,*k,*v,*ql,*kl,*a1,*a3,*a2,*xz,*w,*u,*z,*z2,*t3p,*t3,*t2,*oh;
    int* scal;
    cudaGetSymbolAddress((void**)&q,  g_q);
    cudaGetSymbolAddress((void**)&k,  g_k);
    cudaGetSymbolAddress((void**)&v,  g_v);
    cudaGetSymbolAddress((void**)&ql, g_ql);
    cudaGetSymbolAddress((void**)&kl, g_kl);
    cudaGetSymbolAddress((void**)&a1, g_attn1);
    cudaGetSymbolAddress((void**)&a3, g_attn3);
    cudaGetSymbolAddress((void**)&a2, g_a2);
    cudaGetSymbolAddress((void**)&xz, g_xz);
    cudaGetSymbolAddress((void**)&w,  g_w);
    cudaGetSymbolAddress((void**)&u,  g_u);
    cudaGetSymbolAddress((void**)&z,  g_z);
    cudaGetSymbolAddress((void**)&z2, g_z2);
    cudaGetSymbolAddress((void**)&t3p,g_t3p);
    cudaGetSymbolAddress((void**)&t3, g_t3);
    cudaGetSymbolAddress((void**)&t2, g_t2);
    cudaGetSymbolAddress((void**)&oh, g_oh);
    cudaGetSymbolAddress((void**)&scal, g_scal);

    init_scal_k<<<1, 32>>>(scal);

    // 1. QKV projection: [16384,512]@[512,1536] scattered to head-major q/k/v
    gemm_tc<128,128,64,32,false><<<dim3(12, 128, 1), 256>>>(
        AP{x, DIM, 0}, BP{w_qkv, 1536, 0}, EQKV{q, k, v}, DIM);

    // 2. landmark means
    landmarks_k<<<1024, 256>>>(q, k, ql, kl);

    // 3. sim2 = ql @ kl^T -> softmax -> attn2
    gemm_tc<64,64,32,32,true><<<dim3(4, 4, BHN), 128>>>(
        AP{ql, 64, (size_t)ML*64}, BTmat{kl, 64, (size_t)ML*64},
        ES{a2, 256, 65536, 1.f}, 64);
    softmax256_k<<<BHN*ML, 256>>>(a2);

    // 4. pinv init: scalars + z0 = attn2^T / (col*row)
    scal_reduce_k<<<dim3(256, BHN, 2), 256>>>(a2, scal);
    zinit_k<<<4096, 256>>>(a2, scal, z);

    // 5. Newton–Schulz iterations (4 batched 256^3 GEMMs each)
    for (int it = 0; it < 6; it++) {
        float* zin  = (it & 1) ? z2 : z;
        float* zout = (it & 1) ? z  : z2;
        gemm_tc<64,64,32,32,false><<<dim3(4,4,BHN), 128>>>(
            AP{a2,256,65536}, BP{zin,256,65536}, ES{xz,256,65536,1.f}, 256);
        gemm_tc<64,64,32,32,false><<<dim3(4,4,BHN), 128>>>(
            AP{xz,256,65536}, BDiag{xz,7.f}, EDiag{w,15.f}, 256);
        gemm_tc<64,64,32,32,false><<<dim3(4,4,BHN), 128>>>(
            AP{xz,256,65536}, BP{w,256,65536}, EDiag{u,13.f}, 256);
        gemm_tc<64,64,32,32,false><<<dim3(4,4,BHN), 128>>>(
            AP{zin,256,65536}, BP{u,256,65536}, ES{zout,256,65536,0.25f}, 256);
    }
    // after 6 iters final z lives in g_z

    // 6. attn1 = softmax(q @ kl^T)
    gemm_tc<128,128,64,32,true><<<dim3(2, 64, BHN), 256>>>(
        AP{q, 64, (size_t)NTOK*64}, BTmat{kl, 64, (size_t)ML*64},
        ES{a1, 256, (size_t)NTOK*256, 1.f}, 64);
    softmax256_k<<<BHN*NTOK, 256>>>(a1);

    // 7. sim3 = ql @ k^T -> softmax over n=8192
    gemm_tc<128,128,64,32,true><<<dim3(64, 2, BHN), 256>>>(
        AP{ql, 64, (size_t)ML*64}, BTmat{k, 64, (size_t)NTOK*64},
        ES{a3, NTOK, (size_t)ML*NTOK, 1.f}, 64);
    softmax8192_k<<<BHN*ML, 256>>>(a3);

    // 8. t3 = attn3 @ v  (split-K x16 + reduce)
    gemm_tc<128,64,64,32,false><<<dim3(1, 2, BHN*16), 128>>>(
        ASplit{a3}, BSplit{v}, EPart{t3p}, 512);
    t3_reduce_k<<<1024, 256>>>(t3p, t3);

    // 9. t2 = z @ t3
    gemm_tc<128,64,64,32,false><<<dim3(1, 2, BHN), 128>>>(
        AP{z, 256, 65536}, BP{t3, 64, (size_t)ML*64},
        ES{t2, 64, (size_t)ML*64, 1.f}, 256);

    // 10. oh = attn1 @ t2
    gemm_tc<128,64,64,32,false><<<dim3(1, 64, BHN), 128>>>(
        AP{a1, 256, (size_t)NTOK*256}, BP{t2, 64, (size_t)ML*64},
        ES{oh, 64, (size_t)NTOK*64, 1.f}, 256);

    // 11. residual depthwise conv over sequence, added into oh
    conv_add_k<<<32768, 256>>>(v, w_conv, oh);

    // 12. y = x + (oh gathered to [b,n,512]) @ w_out + b_out
    gemm_tc<128,128,64,32,false><<<dim3(4, 128, 1), 256>>>(
        AGather{oh}, BP{w_out, DIM, 0}, EFin{x, b_out, out}, DIM);
}

// round 4
// speedup vs baseline: 2.2315x; 1.5370x over previous
#include <cuda_runtime.h>
#include <math.h>
#include <stddef.h>
#include <stdint.h>

#define NHEADS 8
#define DIMH   64
#define NTOK   8192
#define BHN    16
#define ML     256
#define LGRP   32
#define DIM    512

// ---------------- scratch ----------------
__device__ float g_q [BHN*NTOK*DIMH];
__device__ float g_k [BHN*NTOK*DIMH];
__device__ float g_v [BHN*NTOK*DIMH];
__device__ float g_ql[BHN*ML*DIMH];
__device__ float g_kl[BHN*ML*DIMH];
__device__ float g_attn1[33554432];   // [bh][8192][256]
__device__ float g_attn3[33554432];   // [bh][256][8192]
__device__ float g_a2 [BHN*ML*ML];
__device__ float g_xz [BHN*ML*ML];
__device__ float g_w  [BHN*ML*ML];
__device__ float g_u  [BHN*ML*ML];
__device__ float g_z  [BHN*ML*ML];
__device__ float g_z2 [BHN*ML*ML];
__device__ float g_t3p[16*BHN*ML*DIMH];
__device__ float g_t3 [BHN*ML*DIMH];
__device__ float g_t2 [BHN*ML*DIMH];
__device__ float g_oh [BHN*NTOK*DIMH];
__device__ int   g_scal[2];

// ---------------- primitives ----------------
__device__ __forceinline__ void mma_tf32(float* d, const unsigned* a, const unsigned* b) {
    asm volatile("mma.sync.aligned.m16n8k8.row.col.f32.tf32.tf32.f32 "
        "{%0,%1,%2,%3}, {%4,%5,%6,%7}, {%8,%9}, {%0,%1,%2,%3};"
        : "+f"(d[0]), "+f"(d[1]), "+f"(d[2]), "+f"(d[3])
        : "r"(a[0]), "r"(a[1]), "r"(a[2]), "r"(a[3]), "r"(b[0]), "r"(b[1]));
}
__device__ __forceinline__ void cp16(uint32_t s, const void* g) {
    asm volatile("cp.async.cg.shared.global [%0], [%1], 16;\n" :: "r"(s), "l"(g));
}
__device__ __forceinline__ void cp_commit() {
    asm volatile("cp.async.commit_group;\n" ::: "memory");
}
__device__ __forceinline__ void cp_wait0() {
    asm volatile("cp.async.wait_group 0;\n" ::: "memory");
}
__device__ __forceinline__ void cp_wait1() {
    asm volatile("cp.async.wait_group 1;\n" ::: "memory");
}
__device__ __forceinline__ uint32_t s2u(const void* p) {
    return (uint32_t)__cvta_generic_to_shared(p);
}

// ---------------- functors (gmem address providers + epilogues) ----------------
struct AP {                 // row-major [*, ld], batch stride bs
    const float* p; int ld; size_t bs;
    __device__ __forceinline__ const void* src(int bz, int r, int k) const {
        return p + (size_t)bz*bs + (size_t)r*ld + k;
    }
};
struct BP {                 // row-major B [K, ld]
    const float* p; int ld; size_t bs;
    __device__ __forceinline__ const void* src(int bz, int k, int n) const {
        return p + (size_t)bz*bs + (size_t)k*ld + n;
    }
};
struct BTmat {              // B stored [N, K] row-major
    const float* p; int ld; size_t bs;
    __device__ __forceinline__ const void* srcT(int bz, int c, int k) const {
        return p + (size_t)bz*bs + (size_t)c*ld + k;
    }
};
struct ASplit {             // attn3 [bh][256][8192], bz = bh*16 + split
    const float* p;
    __device__ __forceinline__ const void* src(int bz, int r, int k) const {
        int bh = bz >> 4, sp = bz & 15;
        return p + ((size_t)bh*ML + r)*NTOK + sp*512 + k;
    }
};
struct BSplit {             // v [bh][8192][64]
    const float* p;
    __device__ __forceinline__ const void* src(int bz, int k, int n) const {
        int bh = bz >> 4, sp = bz & 15;
        return p + ((size_t)bh*NTOK + sp*512 + k)*64 + n;
    }
};
struct AGather {            // oh [bh][t][dd]; row=(b,t), k=head*64+dd
    const float* p;
    __device__ __forceinline__ const void* src(int bz, int r, int k) const {
        int b = r >> 13, t = r & (NTOK-1), head = k >> 6, dd = k & 63;
        return p + (((size_t)(b*8+head))*NTOK + t)*64 + dd;
    }
};
struct ES {
    float* p; int ld; size_t bs; float scale;
    __device__ __forceinline__ void store(int bz, int r, int c, float v) const {
        p[(size_t)bz*bs + (size_t)r*ld + c] = v*scale;
    }
};
struct EDiag {              // alpha*I - acc
    float* p; float alpha;
    __device__ __forceinline__ void store(int bz, int r, int c, float v) const {
        p[(size_t)bz*65536 + (size_t)r*256 + c] = ((r==c)?alpha:0.f) - v;
    }
};
struct EW {                 // w = 15I - 7*xz + acc  (acc = xz@xz)
    const float* xz; float* w;
    __device__ __forceinline__ void store(int bz, int r, int c, float v) const {
        size_t o = (size_t)bz*65536 + (size_t)r*256 + c;
        w[o] = ((r==c)?15.f:0.f) - 7.f*xz[o] + v;
    }
};
struct EQKV {
    float* q; float* k; float* v;
    __device__ __forceinline__ void store(int bz, int r, int c, float acc) const {
        int b = r >> 13, t = r & (NTOK-1);
        int which = c >> 9, head = (c >> 6) & 7, dd = c & 63;
        float* dst = (which==0) ? q : ((which==1) ? k : v);
        if (which == 0) acc *= 0.125f;
        dst[(((size_t)(b*8+head))*NTOK + t)*64 + dd] = acc;
    }
};
struct EPart {
    float* p;
    __device__ __forceinline__ void store(int bz, int r, int c, float v) const {
        int bh = bz >> 4, sp = bz & 15;
        p[(((size_t)sp*BHN + bh)*ML + r)*64 + c] = v;
    }
};
struct EFin {
    const float* x; const float* bo; float* out;
    __device__ __forceinline__ void store(int bz, int r, int c, float v) const {
        size_t i = (size_t)r*DIM + c;
        out[i] = x[i] + bo[c] + v;
    }
};

// ---------------- general tf32 tensor-core GEMM, cp.async double-buffered ---
// A smem row-major [BM][20]; B smem: NN -> [16][BN+4], BT -> [BN][20].
template<int BM, int BN, int WM, int WN, bool BT, class FA, class FB, class FE>
__global__ __launch_bounds__((BM/WM)*(BN/WN)*32)
void gemm_tc(FA fa, FB fb, FE fe, int K) {
    constexpr int NTHR = (BM/WM)*(BN/WN)*32;
    constexpr int LDA = 20;
    constexpr int LDB = BN + 4;
    constexpr int MT = WM/16, NT = WN/8;
    constexpr int BSZ = BT ? 2*BN*20 : 2*16*LDB;
    __shared__ float As[2*BM*LDA];
    __shared__ float Bs[BSZ];
    const int tid = threadIdx.x;
    const int wid = tid >> 5, lane = tid & 31;
    const int qd = lane >> 2, tq = lane & 3;
    const int wm = (wid / (BN/WN)) * WM, wn = (wid % (BN/WN)) * WN;
    const int m0 = blockIdx.y * BM, n0 = blockIdx.x * BN, bz = blockIdx.z;
    const uint32_t sA = s2u(As), sB = s2u(Bs);

    float acc[MT][NT][4] = {};

    auto load_tile = [&](int k0, int buf) {
        const uint32_t ab = sA + buf*BM*LDA*4;
#pragma unroll
        for (int i = tid; i < BM*4; i += NTHR) {
            int r = i >> 2, kq = (i & 3) << 2;
            cp16(ab + (r*LDA + kq)*4, fa.src(bz, m0 + r, k0 + kq));
        }
        if constexpr (BT) {
            const uint32_t bb = sB + buf*BN*20*4;
#pragma unroll
            for (int i = tid; i < BN*4; i += NTHR) {
                int n = i >> 2, kq = (i & 3) << 2;
                cp16(bb + (n*20 + kq)*4, fb.srcT(bz, n0 + n, k0 + kq));
            }
        } else {
            const uint32_t bb = sB + buf*16*LDB*4;
#pragma unroll
            for (int i = tid; i < BN*4; i += NTHR) {
                int kk = i / (BN/4), nq = (i % (BN/4)) * 4;
                cp16(bb + (kk*LDB + nq)*4, fb.src(bz, k0 + kk, n0 + nq));
            }
        }
        cp_commit();
    };

    load_tile(0, 0);
    const int T = K >> 4;
    for (int t = 0; t < T; t++) {
        if (t + 1 < T) { load_tile((t+1) << 4, (t+1) & 1); cp_wait1(); }
        else           { cp_wait0(); }
        __syncthreads();
        const float* Ab = As + (t & 1)*BM*LDA;
        const float* Bb = BT ? (Bs + (t & 1)*BN*20) : (Bs + (t & 1)*16*LDB);
#pragma unroll
        for (int ks = 0; ks < 16; ks += 8) {
            unsigned af[MT][4];
#pragma unroll
            for (int mt = 0; mt < MT; mt++) {
                int mm = wm + mt*16 + qd;
                af[mt][0] = __float_as_uint(Ab[ mm     *LDA + ks + tq    ]);
                af[mt][1] = __float_as_uint(Ab[(mm + 8)*LDA + ks + tq    ]);
                af[mt][2] = __float_as_uint(Ab[ mm     *LDA + ks + tq + 4]);
                af[mt][3] = __float_as_uint(Ab[(mm + 8)*LDA + ks + tq + 4]);
            }
#pragma unroll
            for (int nt = 0; nt < NT; nt++) {
                int nn = wn + nt*8 + qd;
                unsigned bf[2];
                if constexpr (BT) {
                    bf[0] = __float_as_uint(Bb[nn*20 + ks + tq    ]);
                    bf[1] = __float_as_uint(Bb[nn*20 + ks + tq + 4]);
                } else {
                    bf[0] = __float_as_uint(Bb[(ks + tq    )*LDB + nn]);
                    bf[1] = __float_as_uint(Bb[(ks + tq + 4)*LDB + nn]);
                }
#pragma unroll
                for (int mt = 0; mt < MT; mt++)
                    mma_tf32(acc[mt][nt], af[mt], bf);
            }
        }
        __syncthreads();
    }
#pragma unroll
    for (int mt = 0; mt < MT; mt++)
#pragma unroll
        for (int nt = 0; nt < NT; nt++) {
            int r = m0 + wm + mt*16 + qd;
            int c = n0 + wn + nt*8 + tq*2;
            fe.store(bz, r,   c,   acc[mt][nt][0]);
            fe.store(bz, r,   c+1, acc[mt][nt][1]);
            fe.store(bz, r+8, c,   acc[mt][nt][2]);
            fe.store(bz, r+8, c+1, acc[mt][nt][3]);
        }
}

// ---------------- fused GEMM + row softmax: O = softmax(A @ B^T) -----------
// A [*, 64] (M rows), B [256][64], O [*, 256]. BM=128, 8 warps. Whole B in smem.
__global__ __launch_bounds__(256)
void gemm_rowsmax(const float* __restrict__ A, size_t a_bs,
                  const float* __restrict__ B, size_t b_bs,
                  float* __restrict__ O, size_t o_bs) {
    extern __shared__ float sm[];
    float* As = sm;                 // [2][128][20]
    float* Bs = sm + 2*128*20;      // [256][68]
    const int tid = threadIdx.x, wid = tid >> 5, lane = tid & 31;
    const int qd = lane >> 2, tq = lane & 3;
    const int m0 = blockIdx.y * 128, bz = blockIdx.z;
    const float* Ag = A + (size_t)bz * a_bs;
    const float* Bg = B + (size_t)bz * b_bs;
    const uint32_t sA = s2u(As), sB = s2u(Bs);

    // whole B (256x64) + A tile 0 in group 0
#pragma unroll
    for (int i = tid; i < 256*4; i += 256) {
        int n = i >> 2, kq = (i & 3) << 2;
        cp16(sB + (n*68 + kq)*4, Bg + (size_t)n*64 + kq);
    }
#pragma unroll
    for (int i = tid; i < 128*4; i += 256) {
        int r = i >> 2, kq = (i & 3) << 2;
        cp16(sA + (r*20 + kq)*4, Ag + (size_t)(m0 + r)*64 + kq);
    }
    cp_commit();

    float acc[32][4] = {};
    for (int t = 0; t < 4; t++) {
        if (t < 3) {
            const uint32_t ab = sA + ((t+1) & 1)*128*20*4;
            const int k0 = (t+1) << 4;
#pragma unroll
            for (int i = tid; i < 128*4; i += 256) {
                int r = i >> 2, kq = (i & 3) << 2;
                cp16(ab + (r*20 + kq)*4, Ag + (size_t)(m0 + r)*64 + k0 + kq);
            }
            cp_commit();
            cp_wait1();
        } else cp_wait0();
        __syncthreads();
        const float* Ab = As + (t & 1)*128*20;
        const int kb = t << 4;
#pragma unroll
        for (int ks = 0; ks < 16; ks += 8) {
            unsigned af[4];
            int mm = wid*16 + qd;
            af[0] = __float_as_uint(Ab[ mm     *20 + ks + tq    ]);
            af[1] = __float_as_uint(Ab[(mm + 8)*20 + ks + tq    ]);
            af[2] = __float_as_uint(Ab[ mm     *20 + ks + tq + 4]);
            af[3] = __float_as_uint(Ab[(mm + 8)*20 + ks + tq + 4]);
#pragma unroll
            for (int nt = 0; nt < 32; nt++) {
                int nn = nt*8 + qd;
                unsigned bf[2];
                bf[0] = __float_as_uint(Bs[nn*68 + kb + ks + tq    ]);
                bf[1] = __float_as_uint(Bs[nn*68 + kb + ks + tq + 4]);
                mma_tf32(acc[nt], af, bf);
            }
        }
        __syncthreads();
    }
    // row softmax: row r0 owned by the 4 lanes of this quad (tq=0..3)
    float mx0 = -1e30f, mx1 = -1e30f;
#pragma unroll
    for (int nt = 0; nt < 32; nt++) {
        mx0 = fmaxf(mx0, fmaxf(acc[nt][0], acc[nt][1]));
        mx1 = fmaxf(mx1, fmaxf(acc[nt][2], acc[nt][3]));
    }
#pragma unroll
    for (int s = 1; s < 4; s <<= 1) {
        mx0 = fmaxf(mx0, __shfl_xor_sync(0xffffffffu, mx0, s));
        mx1 = fmaxf(mx1, __shfl_xor_sync(0xffffffffu, mx1, s));
    }
    float s0 = 0.f, s1 = 0.f;
#pragma unroll
    for (int nt = 0; nt < 32; nt++) {
        acc[nt][0] = __expf(acc[nt][0] - mx0);
        acc[nt][1] = __expf(acc[nt][1] - mx0);
        acc[nt][2] = __expf(acc[nt][2] - mx1);
        acc[nt][3] = __expf(acc[nt][3] - mx1);
        s0 += acc[nt][0] + acc[nt][1];
        s1 += acc[nt][2] + acc[nt][3];
    }
#pragma unroll
    for (int s = 1; s < 4; s <<= 1) {
        s0 += __shfl_xor_sync(0xffffffffu, s0, s);
        s1 += __shfl_xor_sync(0xffffffffu, s1, s);
    }
    const float i0 = 1.f / s0, i1 = 1.f / s1;
    const int r0 = m0 + wid*16 + qd;
    float* O0 = O + (size_t)bz*o_bs + (size_t)r0*256;
#pragma unroll
    for (int nt = 0; nt < 32; nt++) {
        int c = nt*8 + tq*2;
        *(float2*)(O0 + c)         = make_float2(acc[nt][0]*i0, acc[nt][1]*i0);
        *(float2*)(O0 + 8*256 + c) = make_float2(acc[nt][2]*i1, acc[nt][3]*i1);
    }
}

// ---------------- small kernels ----------------
__global__ void init_scal_k(int* scal) { if (threadIdx.x < 2) scal[threadIdx.x] = 0; }

__global__ __launch_bounds__(256) void landmarks_k(
        const float* __restrict__ q, const float* __restrict__ k,
        float* __restrict__ ql, float* __restrict__ kl) {
    int idx = blockIdx.x * 256 + threadIdx.x;
    int dd = idx & 63, j = (idx >> 6) & 255, bh = idx >> 14;
    const float* qp = q + ((size_t)bh*NTOK + (size_t)j*LGRP)*64 + dd;
    const float* kp = k + ((size_t)bh*NTOK + (size_t)j*LGRP)*64 + dd;
    float sq = 0.f, sk = 0.f;
#pragma unroll
    for (int t = 0; t < LGRP; t++) { sq += qp[(size_t)t*64]; sk += kp[(size_t)t*64]; }
    ql[idx] = sq * (1.f/LGRP);
    kl[idx] = sk * (1.f/LGRP);
}

__global__ __launch_bounds__(256) void scal_reduce_k(const float* __restrict__ a2, int* scal) {
    int idx = blockIdx.x, bh = blockIdx.y, mode = blockIdx.z, tid = threadIdx.x;
    const float* base = a2 + (size_t)bh * 65536;
    float v = (mode == 0) ? base[(size_t)idx*256 + tid] : base[(size_t)tid*256 + idx];
    __shared__ float red[256];
    red[tid] = v; __syncthreads();
    for (int s = 128; s > 0; s >>= 1) { if (tid < s) red[tid] += red[tid+s]; __syncthreads(); }
    if (tid == 0) atomicMax(&scal[mode], __float_as_int(red[0]));
}

__global__ __launch_bounds__(256) void zinit_k(const float* __restrict__ a2,
                                               const int* __restrict__ scal,
                                               float* __restrict__ z) {
    size_t idx = (size_t)blockIdx.x * 256 + threadIdx.x;
    float col = __int_as_float(scal[0]), row = __int_as_float(scal[1]);
    float rcp = 1.f / (col * row);
    int j = (int)(idx & 255), i = (int)((idx >> 8) & 255);
    size_t bh = idx >> 16;
    z[idx] = a2[(bh << 16) + (size_t)j*256 + i] * rcp;
}

__global__ __launch_bounds__(256) void softmax8192_k(float* a) {
    __shared__ float buf[8192];
    __shared__ float red[256];
    float* p = a + (size_t)blockIdx.x * 8192;
    int tid = threadIdx.x;
    float lm = -1e30f;
    for (int j = tid; j < 8192; j += 256) { float v = p[j]; buf[j] = v; lm = fmaxf(lm, v); }
    red[tid] = lm; __syncthreads();
    for (int s = 128; s > 0; s >>= 1) { if (tid < s) red[tid] = fmaxf(red[tid], red[tid+s]); __syncthreads(); }
    float m = red[0]; __syncthreads();
    float ls = 0.f;
    for (int j = tid; j < 8192; j += 256) { float e = __expf(buf[j] - m); buf[j] = e; ls += e; }
    red[tid] = ls; __syncthreads();
    for (int s = 128; s > 0; s >>= 1) { if (tid < s) red[tid] += red[tid+s]; __syncthreads(); }
    float rinv = 1.f / red[0];
    for (int j = tid; j < 8192; j += 256) p[j] = buf[j] * rinv;
}

__global__ __launch_bounds__(256) void t3_reduce_k(const float* __restrict__ part,
                                                   float* __restrict__ t3) {
    int idx = blockIdx.x * 256 + threadIdx.x;
    float s = 0.f;
#pragma unroll
    for (int sp = 0; sp < 16; sp++) s += part[(size_t)sp*262144 + idx];
    t3[idx] = s;
}

__global__ __launch_bounds__(256) void conv_add_k(const float* __restrict__ v,
                                                  const float* __restrict__ wc,
                                                  float* __restrict__ oh) {
    size_t idx = (size_t)blockIdx.x * 256 + threadIdx.x;
    int dd = (int)(idx & 63);
    int i  = (int)((idx >> 6) & (NTOK-1));
    int bh = (int)(idx >> 19);
    int h = bh & 7;
    const float* vb = v + ((size_t)bh * NTOK) * 64 + dd;
    float s = 0.f;
#pragma unroll
    for (int t = 0; t < 33; t++) {
        int src = i + t - 16;
        if (src >= 0 && src < NTOK) s += wc[h*33 + t] * vb[(size_t)src*64];
    }
    oh[idx] += s;
}

// ---------------- orchestration ----------------
extern "C" void kernel_launch(void* const* d_in, const int* in_sizes, int n_in,
                              void* d_out, int out_size) {
    (void)in_sizes; (void)n_in; (void)out_size;
    const float* x      = (const float*)d_in[0];
    const float* w_qkv  = (const float*)d_in[1];
    const float* w_out  = (const float*)d_in[2];
    const float* b_out  = (const float*)d_in[3];
    const float* w_conv = (const float*)d_in[4];
    float* out = (float*)d_out;

    float *q,*k,*v,*ql,*kl,*a1,*a3,*a2,*xz,*w,*u,*z,*z2,*t3p,*t3,*t2,*oh;
    int* scal;
    cudaGetSymbolAddress((void**)&q,  g_q);
    cudaGetSymbolAddress((void**)&k,  g_k);
    cudaGetSymbolAddress((void**)&v,  g_v);
    cudaGetSymbolAddress((void**)&ql, g_ql);
    cudaGetSymbolAddress((void**)&kl, g_kl);
    cudaGetSymbolAddress((void**)&a1, g_attn1);
    cudaGetSymbolAddress((void**)&a3, g_attn3);
    cudaGetSymbolAddress((void**)&a2, g_a2);
    cudaGetSymbolAddress((void**)&xz, g_xz);
    cudaGetSymbolAddress((void**)&w,  g_w);
    cudaGetSymbolAddress((void**)&u,  g_u);
    cudaGetSymbolAddress((void**)&z,  g_z);
    cudaGetSymbolAddress((void**)&z2, g_z2);
    cudaGetSymbolAddress((void**)&t3p,g_t3p);
    cudaGetSymbolAddress((void**)&t3, g_t3);
    cudaGetSymbolAddress((void**)&t2, g_t2);
    cudaGetSymbolAddress((void**)&oh, g_oh);
    cudaGetSymbolAddress((void**)&scal, g_scal);

    static bool attr_done = false;
    if (!attr_done) {
        cudaFuncSetAttribute(gemm_rowsmax,
            cudaFuncAttributeMaxDynamicSharedMemorySize, 90112);
        attr_done = true;
    }

    init_scal_k<<<1, 32>>>(scal);

    // 1. QKV projection
    gemm_tc<128,128,64,32,false><<<dim3(12, 128, 1), 256>>>(
        AP{x, DIM, 0}, BP{w_qkv, 1536, 0}, EQKV{q, k, v}, DIM);

    // 2. landmark means
    landmarks_k<<<1024, 256>>>(q, k, ql, kl);

    // 3. attn2 = softmax(ql @ kl^T), fused
    gemm_rowsmax<<<dim3(1, 2, BHN), 256, 90112>>>(
        ql, (size_t)ML*64, kl, (size_t)ML*64, a2, (size_t)ML*256);

    // 4. pinv init
    scal_reduce_k<<<dim3(256, BHN, 2), 256>>>(a2, scal);
    zinit_k<<<4096, 256>>>(a2, scal, z);

    // 5. Newton–Schulz x6 (BDiag eliminated: w = 15I - 7xz + xz@xz)
    for (int it = 0; it < 6; it++) {
        float* zin  = (it & 1) ? z2 : z;
        float* zout = (it & 1) ? z  : z2;
        gemm_tc<64,64,32,32,false><<<dim3(4,4,BHN), 128>>>(
            AP{a2,256,65536}, BP{zin,256,65536}, ES{xz,256,65536,1.f}, 256);
        gemm_tc<64,64,32,32,false><<<dim3(4,4,BHN), 128>>>(
            AP{xz,256,65536}, BP{xz,256,65536}, EW{xz, w}, 256);
        gemm_tc<64,64,32,32,false><<<dim3(4,4,BHN), 128>>>(
            AP{xz,256,65536}, BP{w,256,65536}, EDiag{u,13.f}, 256);
        gemm_tc<64,64,32,32,false><<<dim3(4,4,BHN), 128>>>(
            AP{zin,256,65536}, BP{u,256,65536}, ES{zout,256,65536,0.25f}, 256);
    }

    // 6. attn1 = softmax(q @ kl^T), fused
    gemm_rowsmax<<<dim3(1, 64, BHN), 256, 90112>>>(
        q, (size_t)NTOK*64, kl, (size_t)ML*64, a1, (size_t)NTOK*256);

    // 7. sim3 = ql @ k^T -> softmax over 8192
    gemm_tc<128,128,64,32,true><<<dim3(64, 2, BHN), 256>>>(
        AP{ql, 64, (size_t)ML*64}, BTmat{k, 64, (size_t)NTOK*64},
        ES{a3, NTOK, (size_t)ML*NTOK, 1.f}, 64);
    softmax8192_k<<<BHN*ML, 256>>>(a3);

    // 8. t3 = attn3 @ v  (split-K x16)
    gemm_tc<128,64,64,32,false><<<dim3(1, 2, BHN*16), 128>>>(
        ASplit{a3}, BSplit{v}, EPart{t3p}, 512);
    t3_reduce_k<<<1024, 256>>>(t3p, t3);

    // 9. t2 = z @ t3
    gemm_tc<128,64,64,32,false><<<dim3(1, 2, BHN), 128>>>(
        AP{z, 256, 65536}, BP{t3, 64, (size_t)ML*64},
        ES{t2, 64, (size_t)ML*64, 1.f}, 256);

    // 10. oh = attn1 @ t2
    gemm_tc<128,64,64,32,false><<<dim3(1, 64, BHN), 128>>>(
        AP{a1, 256, (size_t)NTOK*256}, BP{t2, 64, (size_t)ML*64},
        ES{oh, 64, (size_t)NTOK*64, 1.f}, 256);

    // 11. residual depthwise conv
    conv_add_k<<<32768, 256>>>(v, w_conv, oh);

    // 12. out projection + residual
    gemm_tc<128,128,64,32,false><<<dim3(4, 128, 1), 256>>>(
        AGather{oh}, BP{w_out, DIM, 0}, EFin{x, b_out, out}, DIM);
}

// round 6
// speedup vs baseline: 2.4353x; 1.0913x over previous
#include <cuda_runtime.h>
#include <math.h>
#include <stddef.h>
#include <stdint.h>

#define NHEADS 8
#define DIMH   64
#define NTOK   8192
#define BHN    16
#define ML     256
#define LGRP   32
#define DIM    512

// ---------------- scratch ----------------
__device__ float g_q [BHN*NTOK*DIMH];
__device__ float g_k [BHN*NTOK*DIMH];
__device__ float g_v [BHN*NTOK*DIMH];
__device__ float g_ql[BHN*ML*DIMH];
__device__ float g_kl[BHN*ML*DIMH];
__device__ float g_attn1[33554432];   // [bh][8192][256]
__device__ float g_attn3[33554432];   // [bh][256][8192]
__device__ float g_a2 [BHN*ML*ML];
__device__ float g_xz [BHN*ML*ML];
__device__ float g_w  [BHN*ML*ML];
__device__ float g_u  [BHN*ML*ML];
__device__ float g_z  [BHN*ML*ML];
__device__ float g_z2 [BHN*ML*ML];
__device__ float g_t3p[16*BHN*ML*DIMH];
__device__ float g_t3 [BHN*ML*DIMH];
__device__ float g_t2 [BHN*ML*DIMH];
__device__ float g_oh [BHN*NTOK*DIMH];
__device__ int   g_scal[2];

// ---------------- primitives ----------------
__device__ __forceinline__ void mma_tf32(float* d, const unsigned* a, const unsigned* b) {
    asm volatile("mma.sync.aligned.m16n8k8.row.col.f32.tf32.tf32.f32 "
        "{%0,%1,%2,%3}, {%4,%5,%6,%7}, {%8,%9}, {%0,%1,%2,%3};"
        : "+f"(d[0]), "+f"(d[1]), "+f"(d[2]), "+f"(d[3])
        : "r"(a[0]), "r"(a[1]), "r"(a[2]), "r"(a[3]), "r"(b[0]), "r"(b[1]));
}
__device__ __forceinline__ void cp16(uint32_t s, const void* g) {
    asm volatile("cp.async.cg.shared.global [%0], [%1], 16;\n" :: "r"(s), "l"(g));
}
__device__ __forceinline__ void cp_commit() {
    asm volatile("cp.async.commit_group;\n" ::: "memory");
}
__device__ __forceinline__ void cp_wait0() {
    asm volatile("cp.async.wait_group 0;\n" ::: "memory");
}
__device__ __forceinline__ void cp_wait1() {
    asm volatile("cp.async.wait_group 1;\n" ::: "memory");
}
__device__ __forceinline__ uint32_t s2u(const void* p) {
    return (uint32_t)__cvta_generic_to_shared(p);
}

// ---------------- functors ----------------
struct AP {
    const float* p; int ld; size_t bs;
    __device__ __forceinline__ const void* src(int bz, int r, int k) const {
        return p + (size_t)bz*bs + (size_t)r*ld + k;
    }
};
struct BP {
    const float* p; int ld; size_t bs;
    __device__ __forceinline__ const void* src(int bz, int k, int n) const {
        return p + (size_t)bz*bs + (size_t)k*ld + n;
    }
};
struct BTmat {
    const float* p; int ld; size_t bs;
    __device__ __forceinline__ const void* srcT(int bz, int c, int k) const {
        return p + (size_t)bz*bs + (size_t)c*ld + k;
    }
};
struct ASplit {
    const float* p;
    __device__ __forceinline__ const void* src(int bz, int r, int k) const {
        int bh = bz >> 4, sp = bz & 15;
        return p + ((size_t)bh*ML + r)*NTOK + sp*512 + k;
    }
};
struct BSplit {
    const float* p;
    __device__ __forceinline__ const void* src(int bz, int k, int n) const {
        int bh = bz >> 4, sp = bz & 15;
        return p + ((size_t)bh*NTOK + sp*512 + k)*64 + n;
    }
};
struct AGather {
    const float* p;
    __device__ __forceinline__ const void* src(int bz, int r, int k) const {
        int b = r >> 13, t = r & (NTOK-1), head = k >> 6, dd = k & 63;
        return p + (((size_t)(b*8+head))*NTOK + t)*64 + dd;
    }
};
struct ES {
    float* p; int ld; size_t bs; float scale;
    __device__ __forceinline__ void store(int bz, int r, int c, float v) const {
        p[(size_t)bz*bs + (size_t)r*ld + c] = v*scale;
    }
};
struct EDiag {
    float* p; float alpha;
    __device__ __forceinline__ void store(int bz, int r, int c, float v) const {
        p[(size_t)bz*65536 + (size_t)r*256 + c] = ((r==c)?alpha:0.f) - v;
    }
};
struct EW {                 // w = 15I - 7*xz + acc
    const float* xz; float* w;
    __device__ __forceinline__ void store(int bz, int r, int c, float v) const {
        size_t o = (size_t)bz*65536 + (size_t)r*256 + c;
        w[o] = ((r==c)?15.f:0.f) - 7.f*xz[o] + v;
    }
};
struct EQKV {
    float* q; float* k; float* v;
    __device__ __forceinline__ void store(int bz, int r, int c, float acc) const {
        int b = r >> 13, t = r & (NTOK-1);
        int which = c >> 9, head = (c >> 6) & 7, dd = c & 63;
        float* dst = (which==0) ? q : ((which==1) ? k : v);
        if (which == 0) acc *= 0.125f;
        dst[(((size_t)(b*8+head))*NTOK + t)*64 + dd] = acc;
    }
};
struct EPart {
    float* p;
    __device__ __forceinline__ void store(int bz, int r, int c, float v) const {
        int bh = bz >> 4, sp = bz & 15;
        p[(((size_t)sp*BHN + bh)*ML + r)*64 + c] = v;
    }
};
struct EFin {
    const float* x; const float* bo; float* out;
    __device__ __forceinline__ void store(int bz, int r, int c, float v) const {
        size_t i = (size_t)r*DIM + c;
        out[i] = x[i] + bo[c] + v;
    }
};

// ---------------- general tf32 tensor-core GEMM, cp.async double-buffered ---
template<int BM, int BN, int WM, int WN, bool BT, class FA, class FB, class FE>
__global__ __launch_bounds__((BM/WM)*(BN/WN)*32)
void gemm_tc(FA fa, FB fb, FE fe, int K) {
    constexpr int NTHR = (BM/WM)*(BN/WN)*32;
    constexpr int LDA = 20;
    constexpr int LDB = BN + 4;
    constexpr int MT = WM/16, NT = WN/8;
    constexpr int BSZ = BT ? 2*BN*20 : 2*16*LDB;
    __shared__ float As[2*BM*LDA];
    __shared__ float Bs[BSZ];
    const int tid = threadIdx.x;
    const int wid = tid >> 5, lane = tid & 31;
    const int qd = lane >> 2, tq = lane & 3;
    const int wm = (wid / (BN/WN)) * WM, wn = (wid % (BN/WN)) * WN;
    const int m0 = blockIdx.y * BM, n0 = blockIdx.x * BN, bz = blockIdx.z;
    const uint32_t sA = s2u(As), sB = s2u(Bs);

    float acc[MT][NT][4] = {};

    auto load_tile = [&](int k0, int buf) {
        const uint32_t ab = sA + buf*BM*LDA*4;
#pragma unroll
        for (int i = tid; i < BM*4; i += NTHR) {
            int r = i >> 2, kq = (i & 3) << 2;
            cp16(ab + (r*LDA + kq)*4, fa.src(bz, m0 + r, k0 + kq));
        }
        if constexpr (BT) {
            const uint32_t bb = sB + buf*BN*20*4;
#pragma unroll
            for (int i = tid; i < BN*4; i += NTHR) {
                int n = i >> 2, kq = (i & 3) << 2;
                cp16(bb + (n*20 + kq)*4, fb.srcT(bz, n0 + n, k0 + kq));
            }
        } else {
            const uint32_t bb = sB + buf*16*LDB*4;
#pragma unroll
            for (int i = tid; i < BN*4; i += NTHR) {
                int kk = i / (BN/4), nq = (i % (BN/4)) * 4;
                cp16(bb + (kk*LDB + nq)*4, fb.src(bz, k0 + kk, n0 + nq));
            }
        }
        cp_commit();
    };

    load_tile(0, 0);
    const int T = K >> 4;
    for (int t = 0; t < T; t++) {
        if (t + 1 < T) { load_tile((t+1) << 4, (t+1) & 1); cp_wait1(); }
        else           { cp_wait0(); }
        __syncthreads();
        const float* Ab = As + (t & 1)*BM*LDA;
        const float* Bb = BT ? (Bs + (t & 1)*BN*20) : (Bs + (t & 1)*16*LDB);
#pragma unroll
        for (int ks = 0; ks < 16; ks += 8) {
            unsigned af[MT][4];
#pragma unroll
            for (int mt = 0; mt < MT; mt++) {
                int mm = wm + mt*16 + qd;
                af[mt][0] = __float_as_uint(Ab[ mm     *LDA + ks + tq    ]);
                af[mt][1] = __float_as_uint(Ab[(mm + 8)*LDA + ks + tq    ]);
                af[mt][2] = __float_as_uint(Ab[ mm     *LDA + ks + tq + 4]);
                af[mt][3] = __float_as_uint(Ab[(mm + 8)*LDA + ks + tq + 4]);
            }
#pragma unroll
            for (int nt = 0; nt < NT; nt++) {
                int nn = wn + nt*8 + qd;
                unsigned bf[2];
                if constexpr (BT) {
                    bf[0] = __float_as_uint(Bb[nn*20 + ks + tq    ]);
                    bf[1] = __float_as_uint(Bb[nn*20 + ks + tq + 4]);
                } else {
                    bf[0] = __float_as_uint(Bb[(ks + tq    )*LDB + nn]);
                    bf[1] = __float_as_uint(Bb[(ks + tq + 4)*LDB + nn]);
                }
#pragma unroll
                for (int mt = 0; mt < MT; mt++)
                    mma_tf32(acc[mt][nt], af[mt], bf);
            }
        }
        __syncthreads();
    }
#pragma unroll
    for (int mt = 0; mt < MT; mt++)
#pragma unroll
        for (int nt = 0; nt < NT; nt++) {
            int r = m0 + wm + mt*16 + qd;
            int c = n0 + wn + nt*8 + tq*2;
            fe.store(bz, r,   c,   acc[mt][nt][0]);
            fe.store(bz, r,   c+1, acc[mt][nt][1]);
            fe.store(bz, r+8, c,   acc[mt][nt][2]);
            fe.store(bz, r+8, c+1, acc[mt][nt][3]);
        }
}

// ---------------- fused GEMM + row softmax: O = softmax(A @ B^T) -----------
__global__ __launch_bounds__(256)
void gemm_rowsmax(const float* __restrict__ A, size_t a_bs,
                  const float* __restrict__ B, size_t b_bs,
                  float* __restrict__ O, size_t o_bs) {
    extern __shared__ float sm[];
    float* As = sm;                 // [2][128][20]
    float* Bs = sm + 2*128*20;      // [256][68]
    const int tid = threadIdx.x, wid = tid >> 5, lane = tid & 31;
    const int qd = lane >> 2, tq = lane & 3;
    const int m0 = blockIdx.y * 128, bz = blockIdx.z;
    const float* Ag = A + (size_t)bz * a_bs;
    const float* Bg = B + (size_t)bz * b_bs;
    const uint32_t sA = s2u(As), sB = s2u(Bs);

#pragma unroll
    for (int i = tid; i < 256*4; i += 256) {
        int n = i >> 2, kq = (i & 3) << 2;
        cp16(sB + (n*68 + kq)*4, Bg + (size_t)n*64 + kq);
    }
#pragma unroll
    for (int i = tid; i < 128*4; i += 256) {
        int r = i >> 2, kq = (i & 3) << 2;
        cp16(sA + (r*20 + kq)*4, Ag + (size_t)(m0 + r)*64 + kq);
    }
    cp_commit();

    float acc[32][4] = {};
    for (int t = 0; t < 4; t++) {
        if (t < 3) {
            const uint32_t ab = sA + ((t+1) & 1)*128*20*4;
            const int k0 = (t+1) << 4;
#pragma unroll
            for (int i = tid; i < 128*4; i += 256) {
                int r = i >> 2, kq = (i & 3) << 2;
                cp16(ab + (r*20 + kq)*4, Ag + (size_t)(m0 + r)*64 + k0 + kq);
            }
            cp_commit();
            cp_wait1();
        } else cp_wait0();
        __syncthreads();
        const float* Ab = As + (t & 1)*128*20;
        const int kb = t << 4;
#pragma unroll
        for (int ks = 0; ks < 16; ks += 8) {
            unsigned af[4];
            int mm = wid*16 + qd;
            af[0] = __float_as_uint(Ab[ mm     *20 + ks + tq    ]);
            af[1] = __float_as_uint(Ab[(mm + 8)*20 + ks + tq    ]);
            af[2] = __float_as_uint(Ab[ mm     *20 + ks + tq + 4]);
            af[3] = __float_as_uint(Ab[(mm + 8)*20 + ks + tq + 4]);
#pragma unroll
            for (int nt = 0; nt < 32; nt++) {
                int nn = nt*8 + qd;
                unsigned bf[2];
                bf[0] = __float_as_uint(Bs[nn*68 + kb + ks + tq    ]);
                bf[1] = __float_as_uint(Bs[nn*68 + kb + ks + tq + 4]);
                mma_tf32(acc[nt], af, bf);
            }
        }
        __syncthreads();
    }
    float mx0 = -1e30f, mx1 = -1e30f;
#pragma unroll
    for (int nt = 0; nt < 32; nt++) {
        mx0 = fmaxf(mx0, fmaxf(acc[nt][0], acc[nt][1]));
        mx1 = fmaxf(mx1, fmaxf(acc[nt][2], acc[nt][3]));
    }
#pragma unroll
    for (int s = 1; s < 4; s <<= 1) {
        mx0 = fmaxf(mx0, __shfl_xor_sync(0xffffffffu, mx0, s));
        mx1 = fmaxf(mx1, __shfl_xor_sync(0xffffffffu, mx1, s));
    }
    float s0 = 0.f, s1 = 0.f;
#pragma unroll
    for (int nt = 0; nt < 32; nt++) {
        acc[nt][0] = __expf(acc[nt][0] - mx0);
        acc[nt][1] = __expf(acc[nt][1] - mx0);
        acc[nt][2] = __expf(acc[nt][2] - mx1);
        acc[nt][3] = __expf(acc[nt][3] - mx1);
        s0 += acc[nt][0] + acc[nt][1];
        s1 += acc[nt][2] + acc[nt][3];
    }
#pragma unroll
    for (int s = 1; s < 4; s <<= 1) {
        s0 += __shfl_xor_sync(0xffffffffu, s0, s);
        s1 += __shfl_xor_sync(0xffffffffu, s1, s);
    }
    const float i0 = 1.f / s0, i1 = 1.f / s1;
    const int r0 = m0 + wid*16 + qd;
    float* O0 = O + (size_t)bz*o_bs + (size_t)r0*256;
#pragma unroll
    for (int nt = 0; nt < 32; nt++) {
        int c = nt*8 + tq*2;
        *(float2*)(O0 + c)         = make_float2(acc[nt][0]*i0, acc[nt][1]*i0);
        *(float2*)(O0 + 8*256 + c) = make_float2(acc[nt][2]*i1, acc[nt][3]*i1);
    }
}

// ---------------- small kernels ----------------
__global__ void init_scal_k(int* scal) { if (threadIdx.x < 2) scal[threadIdx.x] = 0; }

__global__ __launch_bounds__(256) void landmarks_k(
        const float* __restrict__ q, const float* __restrict__ k,
        float* __restrict__ ql, float* __restrict__ kl) {
    int idx = blockIdx.x * 256 + threadIdx.x;
    int dd = idx & 63, j = (idx >> 6) & 255, bh = idx >> 14;
    const float* qp = q + ((size_t)bh*NTOK + (size_t)j*LGRP)*64 + dd;
    const float* kp = k + ((size_t)bh*NTOK + (size_t)j*LGRP)*64 + dd;
    float sq = 0.f, sk = 0.f;
#pragma unroll
    for (int t = 0; t < LGRP; t++) { sq += qp[(size_t)t*64]; sk += kp[(size_t)t*64]; }
    ql[idx] = sq * (1.f/LGRP);
    kl[idx] = sk * (1.f/LGRP);
}

__global__ __launch_bounds__(256) void scal_reduce_k(const float* __restrict__ a2, int* scal) {
    int idx = blockIdx.x, bh = blockIdx.y, mode = blockIdx.z, tid = threadIdx.x;
    const float* base = a2 + (size_t)bh * 65536;
    float v = (mode == 0) ? base[(size_t)idx*256 + tid] : base[(size_t)tid*256 + idx];
    __shared__ float red[256];
    red[tid] = v; __syncthreads();
    for (int s = 128; s > 0; s >>= 1) { if (tid < s) red[tid] += red[tid+s]; __syncthreads(); }
    if (tid == 0) atomicMax(&scal[mode], __float_as_int(red[0]));
}

__global__ __launch_bounds__(256) void zinit_k(const float* __restrict__ a2,
                                               const int* __restrict__ scal,
                                               float* __restrict__ z) {
    size_t idx = (size_t)blockIdx.x * 256 + threadIdx.x;
    float col = __int_as_float(scal[0]), row = __int_as_float(scal[1]);
    float rcp = 1.f / (col * row);
    int j = (int)(idx & 255), i = (int)((idx >> 8) & 255);
    size_t bh = idx >> 16;
    z[idx] = a2[(bh << 16) + (size_t)j*256 + i] * rcp;
}

__global__ __launch_bounds__(256) void softmax8192_k(float* a) {
    __shared__ float buf[8192];
    __shared__ float red[256];
    float* p = a + (size_t)blockIdx.x * 8192;
    int tid = threadIdx.x;
    float lm = -1e30f;
    for (int j = tid; j < 8192; j += 256) { float v = p[j]; buf[j] = v; lm = fmaxf(lm, v); }
    red[tid] = lm; __syncthreads();
    for (int s = 128; s > 0; s >>= 1) { if (tid < s) red[tid] = fmaxf(red[tid], red[tid+s]); __syncthreads(); }
    float m = red[0]; __syncthreads();
    float ls = 0.f;
    for (int j = tid; j < 8192; j += 256) { float e = __expf(buf[j] - m); buf[j] = e; ls += e; }
    red[tid] = ls; __syncthreads();
    for (int s = 128; s > 0; s >>= 1) { if (tid < s) red[tid] += red[tid+s]; __syncthreads(); }
    float rinv = 1.f / red[0];
    for (int j = tid; j < 8192; j += 256) p[j] = buf[j] * rinv;
}

__global__ __launch_bounds__(256) void t3_reduce_k(const float* __restrict__ part,
                                                   float* __restrict__ t3) {
    int idx = blockIdx.x * 256 + threadIdx.x;
    float s = 0.f;
#pragma unroll
    for (int sp = 0; sp < 16; sp++) s += part[(size_t)sp*262144 + idx];
    t3[idx] = s;
}

__global__ __launch_bounds__(256) void conv_add_k(const float* __restrict__ v,
                                                  const float* __restrict__ wc,
                                                  float* __restrict__ oh) {
    size_t idx = (size_t)blockIdx.x * 256 + threadIdx.x;
    int dd = (int)(idx & 63);
    int i  = (int)((idx >> 6) & (NTOK-1));
    int bh = (int)(idx >> 19);
    int h = bh & 7;
    const float* vb = v + ((size_t)bh * NTOK) * 64 + dd;
    float s = 0.f;
#pragma unroll
    for (int t = 0; t < 33; t++) {
        int src = i + t - 16;
        if (src >= 0 && src < NTOK) s += wc[h*33 + t] * vb[(size_t)src*64];
    }
    oh[idx] += s;
}

// ---------------- orchestration ----------------
extern "C" void kernel_launch(void* const* d_in, const int* in_sizes, int n_in,
                              void* d_out, int out_size) {
    (void)in_sizes; (void)n_in; (void)out_size;
    const float* x      = (const float*)d_in[0];
    const float* w_qkv  = (const float*)d_in[1];
    const float* w_out  = (const float*)d_in[2];
    const float* b_out  = (const float*)d_in[3];
    const float* w_conv = (const float*)d_in[4];
    float* out = (float*)d_out;

    float *q,*k,*v,*ql,*kl,*a1,*a3,*a2,*xz,*w,*u,*z,*z2,*t3p,*t3,*t2,*oh;
    int* scal;
    cudaGetSymbolAddress((void**)&q,  g_q);
    cudaGetSymbolAddress((void**)&k,  g_k);
    cudaGetSymbolAddress((void**)&v,  g_v);
    cudaGetSymbolAddress((void**)&ql, g_ql);
    cudaGetSymbolAddress((void**)&kl, g_kl);
    cudaGetSymbolAddress((void**)&a1, g_attn1);
    cudaGetSymbolAddress((void**)&a3, g_attn3);
    cudaGetSymbolAddress((void**)&a2, g_a2);
    cudaGetSymbolAddress((void**)&xz, g_xz);
    cudaGetSymbolAddress((void**)&w,  g_w);
    cudaGetSymbolAddress((void**)&u,  g_u);
    cudaGetSymbolAddress((void**)&z,  g_z);
    cudaGetSymbolAddress((void**)&z2, g_z2);
    cudaGetSymbolAddress((void**)&t3p,g_t3p);
    cudaGetSymbolAddress((void**)&t3, g_t3);
    cudaGetSymbolAddress((void**)&t2, g_t2);
    cudaGetSymbolAddress((void**)&oh, g_oh);
    cudaGetSymbolAddress((void**)&scal, g_scal);

    static bool attr_done = false;
    if (!attr_done) {
        cudaFuncSetAttribute(gemm_rowsmax,
            cudaFuncAttributeMaxDynamicSharedMemorySize, 90112);
        attr_done = true;
    }

    init_scal_k<<<1, 32>>>(scal);

    // 1. QKV projection (retiled 128x128, 4 warps of 64x64)
    gemm_tc<128,128,64,64,false><<<dim3(12, 128, 1), 128>>>(
        AP{x, DIM, 0}, BP{w_qkv, 1536, 0}, EQKV{q, k, v}, DIM);

    // 2. landmark means
    landmarks_k<<<1024, 256>>>(q, k, ql, kl);

    // 3. attn2 = softmax(ql @ kl^T), fused
    gemm_rowsmax<<<dim3(1, 2, BHN), 256, 90112>>>(
        ql, (size_t)ML*64, kl, (size_t)ML*64, a2, (size_t)ML*256);

    // 4. pinv init
    scal_reduce_k<<<dim3(256, BHN, 2), 256>>>(a2, scal);
    zinit_k<<<4096, 256>>>(a2, scal, z);

    // 5. Newton–Schulz x6
    for (int it = 0; it < 6; it++) {
        float* zin  = (it & 1) ? z2 : z;
        float* zout = (it & 1) ? z  : z2;
        gemm_tc<64,64,32,32,false><<<dim3(4,4,BHN), 128>>>(
            AP{a2,256,65536}, BP{zin,256,65536}, ES{xz,256,65536,1.f}, 256);
        gemm_tc<64,64,32,32,false><<<dim3(4,4,BHN), 128>>>(
            AP{xz,256,65536}, BP{xz,256,65536}, EW{xz, w}, 256);
        gemm_tc<64,64,32,32,false><<<dim3(4,4,BHN), 128>>>(
            AP{xz,256,65536}, BP{w,256,65536}, EDiag{u,13.f}, 256);
        gemm_tc<64,64,32,32,false><<<dim3(4,4,BHN), 128>>>(
            AP{zin,256,65536}, BP{u,256,65536}, ES{zout,256,65536,0.25f}, 256);
    }

    // 6. attn1 = softmax(q @ kl^T), fused softmax
    gemm_rowsmax<<<dim3(1, 64, BHN), 256, 90112>>>(
        q, (size_t)NTOK*64, kl, (size_t)ML*64, a1, (size_t)NTOK*256);

    // 7. sim3 = ql @ k^T -> softmax over 8192 (retiled)
    gemm_tc<128,128,64,64,true><<<dim3(64, 2, BHN), 128>>>(
        AP{ql, 64, (size_t)ML*64}, BTmat{k, 64, (size_t)NTOK*64},
        ES{a3, NTOK, (size_t)ML*NTOK, 1.f}, 64);
    softmax8192_k<<<BHN*ML, 256>>>(a3);

    // 8. t3 = attn3 @ v (split-K x16)
    gemm_tc<128,64,64,32,false><<<dim3(1, 2, BHN*16), 128>>>(
        ASplit{a3}, BSplit{v}, EPart{t3p}, 512);
    t3_reduce_k<<<1024, 256>>>(t3p, t3);

    // 9. t2 = z @ t3
    gemm_tc<128,64,64,32,false><<<dim3(1, 2, BHN), 128>>>(
        AP{z, 256, 65536}, BP{t3, 64, (size_t)ML*64},
        ES{t2, 64, (size_t)ML*64, 1.f}, 256);

    // 10. oh = attn1 @ t2
    gemm_tc<128,64,64,32,false><<<dim3(1, 64, BHN), 128>>>(
        AP{a1, 256, (size_t)NTOK*256}, BP{t2, 64, (size_t)ML*64},
        ES{oh, 64, (size_t)NTOK*64, 1.f}, 256);

    // 11. residual depthwise conv
    conv_add_k<<<32768, 256>>>(v, w_conv, oh);

    // 12. out projection + residual (retiled)
    gemm_tc<128,128,64,64,false><<<dim3(4, 128, 1), 128>>>(
        AGather{oh}, BP{w_out, DIM, 0}, EFin{x, b_out, out}, DIM);
}